// round 16
// baseline (speedup 1.0000x reference)
#include <cuda_runtime.h>
#include <cuda_fp16.h>
#include <math.h>

#define Hh   512
#define Rr   4
#define Ww   32
#define Nn   64
#define Bb   64
#define Tt   256
#define HIDC 759
#define G4C  3036
#define G4E  2048
#define EPSf 1e-6f

#define NBLK 128

// packed-k geometry: h occupies k 0..758, zero pad 759..767, rv at k 768..895
#define DKP  448            // dnc k-pairs (896/2); h-part = kpairs 0..383, rv = 384..447
#define EKP  256            // enc k-pairs (512/2)
#define DSTR 452            // dnc SMEM row stride (u32), 452 % 32 == 4 -> conflict-free ldmatrix
#define ESTR 260            // enc SMEM row stride (u32), 260 % 32 == 4

typedef unsigned long long ull;

// ---- global buffers ----
__device__ float    g_comb[2][HIDC*Bb];               // fp32 h (machinery interface region used)
__device__ unsigned g_cbH[2][Bb*DKP];                 // dnc packed comb (fp16 pairs) [b][kpair]
__device__ unsigned g_ehH[2][Bb*EKP];                 // enc packed h
__device__ float    g_xprojT[(size_t)Tt*G4E*Bb];      // [t][col][b]
__device__ float    g_eprojT[(size_t)Tt*G4C*Bb];      // [t][col][b]
__device__ float    g_encT  [(size_t)Tt*Hh*Bb];       // [t][j][b]

__device__ unsigned g_cnt1[8*32];
__device__ unsigned g_cnt2;
__device__ volatile unsigned g_gen;

__device__ __forceinline__ float sigm(float x)  { return 1.f/(1.f+expf(-x)); }
__device__ __forceinline__ float splus(float x) { return x > 0.f ? x + log1pf(expf(-x)) : log1pf(expf(x)); }

__device__ __forceinline__ float wred_max(float v) {
#pragma unroll
    for (int s = 16; s > 0; s >>= 1) v = fmaxf(v, __shfl_xor_sync(0xffffffffu, v, s));
    return v;
}
__device__ __forceinline__ float wred_sum(float v) {
#pragma unroll
    for (int s = 16; s > 0; s >>= 1) v += __shfl_xor_sync(0xffffffffu, v, s);
    return v;
}

__device__ __forceinline__ unsigned pack_h2(float v0, float v1) {
    __half2 h = __floats2half2_rn(v0, v1);
    return *(unsigned*)&h;
}

__device__ __forceinline__ void mma_f16(float c[4], const unsigned a[4], const unsigned* b) {
    asm volatile("mma.sync.aligned.m16n8k16.row.col.f32.f16.f16.f32 "
        "{%0,%1,%2,%3}, {%4,%5,%6,%7}, {%8,%9}, {%0,%1,%2,%3};"
        : "+f"(c[0]), "+f"(c[1]), "+f"(c[2]), "+f"(c[3])
        : "r"(a[0]), "r"(a[1]), "r"(a[2]), "r"(a[3]), "r"(b[0]), "r"(b[1]));
}

__device__ __forceinline__ void ldsm4(unsigned r[4], unsigned addr) {
    asm volatile("ldmatrix.sync.aligned.m8n8.x4.shared.b16 {%0,%1,%2,%3}, [%4];"
        : "=r"(r[0]), "=r"(r[1]), "=r"(r[2]), "=r"(r[3]) : "r"(addr));
}

__device__ __forceinline__ unsigned smem_u32(const void* p) {
    return (unsigned)__cvta_generic_to_shared(p);
}

#define MBAR256() asm volatile("bar.sync 1, 256;" ::: "memory")   // machinery warps (16-23)
#define MBAR512() asm volatile("bar.sync 3, 512;" ::: "memory")   // matvec warps (0-15), type-A blocks

__device__ __forceinline__ void grid_sync_n(unsigned n) {
    __syncthreads();
    if (threadIdx.x == 0) {
        __threadfence();
        unsigned old = atomicAdd(&g_cnt1[(blockIdx.x & 7) * 32], 1u);
        if (old == n * 16u + 15u) {
            unsigned o2 = atomicAdd(&g_cnt2, 1u);
            if (o2 == n * 8u + 7u) {
                __threadfence();
                g_gen = n + 1u;
            }
        }
        while (g_gen < n + 1u) __nanosleep(32);
        __threadfence();
    }
    __syncthreads();
}

__global__ void zero_bufs() {
    int ncb = 2*Bb*DKP, neh = 2*Bb*EKP;
    int stride = gridDim.x*blockDim.x, tid0 = blockIdx.x*blockDim.x + threadIdx.x;
    for (int i = tid0; i < ncb; i += stride) ((unsigned*)g_cbH)[i] = 0u;
    for (int i = tid0; i < neh; i += stride) ((unsigned*)g_ehH)[i] = 0u;
    if (blockIdx.x == 0) {
        if (threadIdx.x < 8)       g_cnt1[threadIdx.x*32] = 0u;
        else if (threadIdx.x == 8) g_cnt2 = 0u;
        else if (threadIdx.x == 9) g_gen = 0u;
    }
}

// ================= split-tf32 tensor-core prep GEMM (unchanged) =================
__device__ __forceinline__ void split_tf32(float v, float& hi, float& lo) {
    hi = __uint_as_float(__float_as_uint(v) & 0xFFFFE000u);
    lo = v - hi;
}
__device__ __forceinline__ void mma_tf32(float c[4], const unsigned a[4], const unsigned b[2]) {
    asm volatile("mma.sync.aligned.m16n8k8.row.col.f32.tf32.tf32.f32 "
        "{%0,%1,%2,%3}, {%4,%5,%6,%7}, {%8,%9}, {%0,%1,%2,%3};"
        : "+f"(c[0]), "+f"(c[1]), "+f"(c[2]), "+f"(c[3])
        : "r"(a[0]), "r"(a[1]), "r"(a[2]), "r"(a[3]), "r"(b[0]), "r"(b[1]));
}

#define GA (128*33)
#define GB (64*33)
#define GEMM_SMEM ((2*GA + 2*GB)*4)

__global__ void __launch_bounds__(256, 1) gemm_tf32(
    const float* __restrict__ x, const float* __restrict__ Wm,
    const float* __restrict__ bias, float* __restrict__ proj,
    int Ncols, int ldw, int xmode)
{
    extern __shared__ __align__(16) float gsm[];
    float* Ah = gsm;
    float* Al = gsm + GA;
    float* Bh = gsm + 2*GA;
    float* Bl = gsm + 2*GA + GB;

    int tid = threadIdx.x, warp = tid >> 5, lane = tid & 31;
    int wm = warp & 3, wn = warp >> 2;
    int g = lane >> 2, tg = lane & 3;
    int row0 = blockIdx.y * 128, col0 = blockIdx.x * 64;

    float acc[2][4][4];
#pragma unroll
    for (int i = 0; i < 2; i++)
#pragma unroll
        for (int j = 0; j < 4; j++)
#pragma unroll
            for (int e = 0; e < 4; e++) acc[i][j][e] = 0.f;

    for (int k0 = 0; k0 < 512; k0 += 32) {
        __syncthreads();
        if (xmode) {
#pragma unroll
            for (int i = 0; i < 4; i++) {
                int q = i*256 + tid;
                int m = q >> 3, kk = (q & 7) * 4;
                int r = row0 + m;
                float4 v = *(const float4*)(x + ((size_t)(r & 63) * Tt + (r >> 6)) * Hh + k0 + kk);
                float h, l;
                split_tf32(v.x, h, l); Ah[m*33+kk  ] = h; Al[m*33+kk  ] = l;
                split_tf32(v.y, h, l); Ah[m*33+kk+1] = h; Al[m*33+kk+1] = l;
                split_tf32(v.z, h, l); Ah[m*33+kk+2] = h; Al[m*33+kk+2] = l;
                split_tf32(v.w, h, l); Ah[m*33+kk+3] = h; Al[m*33+kk+3] = l;
            }
        } else {
#pragma unroll
            for (int i = 0; i < 4; i++) {
                int q = i*256 + tid;
                int tt = q >> 9, kk = (q >> 4) & 31, b4 = (q & 15) * 4;
                float4 v = *(const float4*)(g_encT + ((size_t)((row0 >> 6) + tt) * Hh + k0 + kk) * Bb + b4);
                int m = tt*64 + b4;
                float h, l;
                split_tf32(v.x, h, l); Ah[(m  )*33+kk] = h; Al[(m  )*33+kk] = l;
                split_tf32(v.y, h, l); Ah[(m+1)*33+kk] = h; Al[(m+1)*33+kk] = l;
                split_tf32(v.z, h, l); Ah[(m+2)*33+kk] = h; Al[(m+2)*33+kk] = l;
                split_tf32(v.w, h, l); Ah[(m+3)*33+kk] = h; Al[(m+3)*33+kk] = l;
            }
        }
#pragma unroll
        for (int i = 0; i < 2; i++) {
            int q = i*256 + tid;
            int cc = q >> 3, kk = (q & 7) * 4;
            int cg = col0 + cc;
            float4 v = make_float4(0.f, 0.f, 0.f, 0.f);
            if (cg < Ncols) v = *(const float4*)(Wm + (size_t)cg * ldw + k0 + kk);
            float h, l;
            split_tf32(v.x, h, l); Bh[cc*33+kk  ] = h; Bl[cc*33+kk  ] = l;
            split_tf32(v.y, h, l); Bh[cc*33+kk+1] = h; Bl[cc*33+kk+1] = l;
            split_tf32(v.z, h, l); Bh[cc*33+kk+2] = h; Bl[cc*33+kk+2] = l;
            split_tf32(v.w, h, l); Bh[cc*33+kk+3] = h; Bl[cc*33+kk+3] = l;
        }
        __syncthreads();

#pragma unroll
        for (int kg = 0; kg < 4; kg++) {
            int kb = kg*8;
            unsigned ah[2][4], al[2][4], bh[4][2], bl[4][2];
#pragma unroll
            for (int mt = 0; mt < 2; mt++) {
                int r0 = (wm*32 + mt*16 + g) * 33 + kb + tg;
                int r1 = r0 + 8*33;
                ah[mt][0] = __float_as_uint(Ah[r0]);
                ah[mt][1] = __float_as_uint(Ah[r1]);
                ah[mt][2] = __float_as_uint(Ah[r0 + 4]);
                ah[mt][3] = __float_as_uint(Ah[r1 + 4]);
                al[mt][0] = __float_as_uint(Al[r0]);
                al[mt][1] = __float_as_uint(Al[r1]);
                al[mt][2] = __float_as_uint(Al[r0 + 4]);
                al[mt][3] = __float_as_uint(Al[r1 + 4]);
            }
#pragma unroll
            for (int nt = 0; nt < 4; nt++) {
                int ci = (wn*32 + nt*8 + g) * 33 + kb + tg;
                bh[nt][0] = __float_as_uint(Bh[ci]);
                bh[nt][1] = __float_as_uint(Bh[ci + 4]);
                bl[nt][0] = __float_as_uint(Bl[ci]);
                bl[nt][1] = __float_as_uint(Bl[ci + 4]);
            }
#pragma unroll
            for (int mt = 0; mt < 2; mt++)
#pragma unroll
                for (int nt = 0; nt < 4; nt++) {
                    mma_tf32(acc[mt][nt], ah[mt], bh[nt]);
                    mma_tf32(acc[mt][nt], ah[mt], bl[nt]);
                    mma_tf32(acc[mt][nt], al[mt], bh[nt]);
                }
        }
    }
#pragma unroll
    for (int mt = 0; mt < 2; mt++) {
        int rbase = row0 + wm*32 + mt*16 + g;
#pragma unroll
        for (int nt = 0; nt < 4; nt++) {
            int cb = col0 + wn*32 + nt*8 + 2*tg;
#pragma unroll
            for (int e = 0; e < 4; e++) {
                int r = rbase + ((e >= 2) ? 8 : 0);
                int cix = cb + (e & 1);
                if (cix < Ncols)
                    proj[((size_t)(r >> 6) * Ncols + cix) * Bb + (r & 63)] = acc[mt][nt][e] + bias[cix];
            }
        }
    }
}

// ============ persistent encoder: 128 blocks x 512 threads (mt4 x nt2 x ks2), full-A resident ============
#define E_SM_U32 (16*ESTR + 64*ESTR + 1024)

__global__ void __launch_bounds__(512, 1) enc_persist(const float* __restrict__ Whh) {
    extern __shared__ __align__(16) unsigned smu[];
    unsigned* BpkH = smu;                  // 16 x ESTR
    unsigned* Apk  = BpkH + 16*ESTR;       // 64 x ESTR
    float*    red  = (float*)(Apk + 64*ESTR);  // 1024

    int tid = threadIdx.x, bid = blockIdx.x;
    int jb = bid * 4;
    int warp = tid >> 5, lane = tid & 31;
    int mt = warp & 3, nt = (warp >> 2) & 1, ks = warp >> 3;
    int g = lane >> 2, tg = lane & 3;
    int S = tg & 1, jh = tg >> 1;
    int b = mt*16 + g + 8*S;
    int j = jb + nt*2 + jh;

    for (int idx = tid; idx < 16*EKP; idx += 512) {
        int c = idx >> 8, kp = idx & 255;
        int jl = c >> 2, gg = c & 3;
        int jw = jb + jl;
        float v0 = Whh[((size_t)(gg*Hh + jw))*Hh + 2*kp];
        float v1 = Whh[((size_t)(gg*Hh + jw))*Hh + 2*kp + 1];
        BpkH[c*ESTR + kp] = pack_h2(v0, v1);
    }
    float cst = 0.f;

    int rowA = mt*16 + (lane & 15);
    unsigned aB = smem_u32(Apk) + (unsigned)(rowA*ESTR + (lane >> 4)*4)*4u;
    int rowB = nt*8 + (lane & 7);
    unsigned bB = smem_u32(BpkH) + (unsigned)(rowB*ESTR + ((lane >> 3)&3)*4)*4u;

    for (int t = 0; t < Tt; t++) {
        int par = t & 1;
        const unsigned* srcH = g_ehH[par];

        const float* xp = g_xprojT + (size_t)t*G4E*Bb;
        float pj0 = __ldg(&xp[((size_t)(0*Hh + j))*Bb + b]);
        float pj1 = __ldg(&xp[((size_t)(1*Hh + j))*Bb + b]);
        float pj2 = __ldg(&xp[((size_t)(2*Hh + j))*Bb + b]);
        float pj3 = __ldg(&xp[((size_t)(3*Hh + j))*Bb + b]);

#pragma unroll
        for (int i = 0; i < 8; i++) {
            int q = i*512 + tid;
            int row = q >> 6, c4 = q & 63;
            *(uint4*)(Apk + row*ESTR + c4*4) = *(const uint4*)(srcH + row*EKP + c4*4);
        }
        __syncthreads();

        float D[4] = {0.f, 0.f, 0.f, 0.f};
#pragma unroll
        for (int q = 0; q < 8; q++) {
            unsigned off = (unsigned)(ks*8 + q)*64u;
            unsigned ah0[4], ah1[4], bhf[4];
            ldsm4(ah0, aB + off);
            ldsm4(ah1, aB + off + 32u);
            ldsm4(bhf, bB + off);
            mma_f16(D, ah0, bhf);
            mma_f16(D, ah1, bhf+2);
        }
        int rslot = ((mt + 4*nt)*32 + lane)*4;
        if (ks == 1) *(float4*)&red[rslot] = make_float4(D[0], D[1], D[2], D[3]);
        __syncthreads();
        if (ks == 0) {
            float4 rr = *(const float4*)&red[rslot];
            D[0] += rr.x; D[1] += rr.y; D[2] += rr.z; D[3] += rr.w;
            float p0 = __shfl_xor_sync(0xffffffffu, D[0], 1);
            float p1 = __shfl_xor_sync(0xffffffffu, D[1], 1);
            float p2 = __shfl_xor_sync(0xffffffffu, D[2], 1);
            float p3 = __shfl_xor_sync(0xffffffffu, D[3], 1);
            float ai, af, ag, ao;
            if (S == 0) { ai = D[0]; af = D[1]; ag = p0; ao = p1; }
            else        { ai = p2;  af = p3;  ag = D[2]; ao = D[3]; }
            float gi = pj0 + ai, gf = pj1 + af, gg = pj2 + ag, go = pj3 + ao;
            cst = sigm(gf)*cst + sigm(gi)*tanhf(gg);
            float hn = sigm(go)*tanhf(cst);
            g_encT[((size_t)t*Hh + j)*Bb + b] = hn;
            float hn2 = __shfl_xor_sync(0xffffffffu, hn, 2);
            if (jh == 0) {
                int kp = (jb + nt*2) >> 1;
                g_ehH[par^1][b*EKP + kp] = pack_h2(hn, hn2);
            }
        }
        grid_sync_n(t);
    }
}

// ============ persistent DNC: 128 blocks x 768 threads, machinery overlapped with h-matvec ============
#define MEM_F  8512
#define D_SM_U32 (24*DSTR + 64*DSTR + 1536 + MEM_F)

__global__ void __launch_bounds__(768, 1) dnc_persist(const float* __restrict__ Whh_c,
                                                      const float* __restrict__ Wih_c,
                                                      float* __restrict__ out) {
    extern __shared__ __align__(16) unsigned smu[];
    unsigned* BpkH = smu;                  // 24 x DSTR
    unsigned* Apk  = BpkH + 24*DSTR;       // 64 x DSTR
    float*    red  = (float*)(Apk + 64*DSTR);  // 1536
    float*    MEM  = red + 1536;

    float* Ms   = MEM;
    float* Ls   = MEM + 2112;
    float* u_s  = MEM + 6272;
    float* p_s  = u_s + 64;
    float* wwo  = p_s + 64;
    float* wwn  = wwo + 64;
    float* su   = wwn + 64;
    float* asrt = su + 64;
    float* cwv  = asrt + 64;
    float* simv = cwv + 64;
    float* mno  = simv + 64;
    int*   rnk  = (int*)(mno + 64);
    float* wro  = mno + 128;
    float* wrn  = wro + 256;
    float* crs  = wrn + 256;
    float* fws  = crs + 256;
    float* bws  = fws + 256;
    float* rk   = bws + 256;
    float* wk   = rk + 128;
    float* er   = wk + 32;
    float* wv   = er + 32;
    float* rs   = wv + 32;
    float* fg   = rs + 4;
    float* rmm  = fg + 4;
    float* rmraw= rmm + 12;
    float* scal = rmraw + 12;

    int tid = threadIdx.x, bid = blockIdx.x;
    int jb = bid * 6;
    int warp = tid >> 5, lane = tid & 31;
    bool typeA = bid < 64;
    int mt = warp & 3;
    int ntks = warp >> 2;                 // 0..5
    int nt, ks;
    if (typeA) { nt = ntks; ks = 0; }                 // warps 0..11 matvec; 16..23 machinery
    else       { nt = ntks % 3; ks = ntks / 3; }
    int g = lane >> 2, tg = lane & 3;
    int S = tg & 1, jh = tg >> 1;
    int b = mt*16 + g + 8*S;
    int j = jb + nt*2 + jh;
    bool epi_own = warp < 12;             // both types: ks==0 third
    bool jv = epi_own && j < HIDC;
    int jsafe = (epi_own && j < HIDC) ? j : 0;

    // weights -> fp16 packed [col][kpair]; rv now at k 768..895
    for (int idx = tid; idx < 24*DKP; idx += 768) {
        int c = idx / DKP, kp = idx - c*DKP;
        int jl = c >> 2, gg = c & 3;
        int jw = jb + jl;
        float v0 = 0.f, v1 = 0.f;
        if (jw < HIDC) {
            int k0 = 2*kp, k1 = 2*kp + 1;
            if (k0 < HIDC) v0 = Whh_c[((size_t)(gg*HIDC + jw))*HIDC + k0];
            else if (k0 >= 768) v0 = Wih_c[((size_t)(gg*HIDC + jw))*640 + 512 + (k0 - 768)];
            if (k1 < HIDC) v1 = Whh_c[((size_t)(gg*HIDC + jw))*HIDC + k1];
            else if (k1 >= 768) v1 = Wih_c[((size_t)(gg*HIDC + jw))*640 + 512 + (k1 - 768)];
        }
        BpkH[c*DSTR + kp] = pack_h2(v0, v1);
    }
    if (typeA) {
        for (int idx = tid; idx < MEM_F; idx += 768) MEM[idx] = 0.f;
    }
    float cst = 0.f;

    int rowA = mt*16 + (lane & 15);
    unsigned aB = smem_u32(Apk) + (unsigned)(rowA*DSTR + (lane >> 4)*4)*4u;
    int rowB = nt*8 + (lane & 7);
    unsigned bB = smem_u32(BpkH) + (unsigned)(rowB*DSTR + ((lane >> 3)&3)*4)*4u;

    __syncthreads();

    for (int t = 0; t < Tt; t++) {
        int par = t & 1;
        int np = par ^ 1;
        const unsigned* srcH = g_cbH[par];
        unsigned* dstH = g_cbH[np];
        const float* combR = g_comb[par];   // machinery interface source (written iter t-1)
        float* combW = g_comb[np];

        float pj0 = 0.f, pj1 = 0.f, pj2 = 0.f, pj3 = 0.f;
        if (epi_own) {
            const float* ep = g_eprojT + (size_t)t*G4C*Bb;
            pj0 = __ldg(&ep[((size_t)(0*HIDC + jsafe))*Bb + b]);
            pj1 = __ldg(&ep[((size_t)(1*HIDC + jsafe))*Bb + b]);
            pj2 = __ldg(&ep[((size_t)(2*HIDC + jsafe))*Bb + b]);
            pj3 = __ldg(&ep[((size_t)(3*HIDC + jsafe))*Bb + b]);
        }

        float D[4] = {0.f, 0.f, 0.f, 0.f};

        // ================= PHASE 1: h-part matvec  ||  machinery =================
        if (typeA) {
            if (warp < 16) {
                // stage h-part: 64 rows x 96 uint4 = 6144 over 512 threads
#pragma unroll
                for (int i = 0; i < 12; i++) {
                    int q = i*512 + tid;
                    int row = q / 96, c4 = q - row*96;
                    *(uint4*)(Apk + row*DSTR + c4*4) = *(const uint4*)(srcH + row*DKP + c4*4);
                }
                MBAR512();
                if (warp < 12) {
#pragma unroll
                    for (int q = 0; q < 24; q++) {
                        unsigned off = (unsigned)q*64u;
                        unsigned ah0[4], ah1[4], bhf[4];
                        ldsm4(ah0, aB + off);
                        ldsm4(ah1, aB + off + 32u);
                        ldsm4(bhf, bB + off);
                        mma_f16(D, ah0, bhf);
                        mma_f16(D, ah1, bhf+2);
                    }
                }
            } else if (t > 0) {
                // ---------------- machinery (warps 16..23), batch = bid ----------------
                int mtid = tid - 512;
                int mwarp = warp - 16;
                int mb = bid;
                if (mtid < 247) {
                    float v = __ldcg(&combR[(Hh + mtid)*Bb + mb]);
                    if      (mtid < 128) rk[mtid] = tanhf(v);
                    else if (mtid < 132) rs[mtid-128] = splus(v);
                    else if (mtid < 164) wk[mtid-132] = tanhf(v);
                    else if (mtid ==164) scal[0] = splus(v);
                    else if (mtid < 197) er[mtid-165] = sigm(v);
                    else if (mtid < 229) wv[mtid-197] = tanhf(v);
                    else if (mtid < 233) fg[mtid-229] = sigm(v);
                    else if (mtid ==233) scal[1] = sigm(v);
                    else if (mtid ==234) scal[2] = sigm(v);
                    else                 rmraw[mtid-235] = v;
                }
                MBAR256();
                if (mtid < 4) {
                    float x0=rmraw[mtid*3], x1=rmraw[mtid*3+1], x2=rmraw[mtid*3+2];
                    float m = fmaxf(x0, fmaxf(x1, x2));
                    float e0=expf(x0-m), e1=expf(x1-m), e2=expf(x2-m), s=e0+e1+e2;
                    rmm[mtid*3]=e0/s; rmm[mtid*3+1]=e1/s; rmm[mtid*3+2]=e2/s;
                } else if (mtid == 4) {
                    float s = EPSf;
                    for (int w = 0; w < 32; w++) s += wk[w]*wk[w];
                    scal[3] = rsqrtf(s);
                } else if (mtid >= 8 && mtid < 12) {
                    int r = mtid - 8; float s = EPSf;
                    for (int w = 0; w < 32; w++) s += rk[r*32+w]*rk[r*32+w];
                    scal[5+r] = rsqrtf(s);
                } else if (mtid >= 64 && mtid < 128) {
                    int n = mtid - 64;
                    float psi = 1.f;
#pragma unroll
                    for (int r = 0; r < 4; r++) psi *= 1.f - fg[r]*wro[r*64+n];
                    float uo = u_s[n], w = wwo[n];
                    u_s[n] = (uo + w - uo*w) * psi;
                }
                MBAR256();
                if (mtid < 64) {
                    float un = u_s[mtid]; int r = 0;
                    for (int m = 0; m < 64; m++) {
                        float um = u_s[m];
                        r += (um < un) || (um == un && m < mtid);
                    }
                    rnk[mtid] = r;
                    su[r] = un;
                } else if (mtid < 128) {
                    int n = mtid - 64; float ss = EPSf, d = 0.f;
                    for (int w = 0; w < 32; w++) { float m = Ms[n*33+w]; ss += m*m; d += wk[w]*m; }
                    simv[n] = d * rsqrtf(ss) * scal[3];
                }
                MBAR256();
                if (mwarp == 1) {
                    float a0 = su[lane], a1 = su[lane+32];
                    float s0 = a0, s1 = a1;
#pragma unroll
                    for (int d = 1; d < 32; d <<= 1) {
                        float t0 = __shfl_up_sync(0xffffffffu, s0, d);
                        float t1 = __shfl_up_sync(0xffffffffu, s1, d);
                        if (lane >= d) { s0 *= t0; s1 *= t1; }
                    }
                    float tot0 = __shfl_sync(0xffffffffu, s0, 31);
                    float u0 = __shfl_up_sync(0xffffffffu, s0, 1);
                    float u1 = __shfl_up_sync(0xffffffffu, s1, 1);
                    float e0 = lane ? u0 : 1.f;
                    float e1 = (lane ? u1 : 1.f) * tot0;
                    asrt[lane]      = (1.f - a0) * e0;
                    asrt[lane + 32] = (1.f - a1) * e1;
                }
                if (mwarp == 0) {
                    float v0 = simv[lane]*scal[0], v1 = simv[lane+32]*scal[0];
                    float mx = wred_max(fmaxf(v0, v1));
                    float e0 = expf(v0 - mx), e1 = expf(v1 - mx);
                    float inv = 1.f / wred_sum(e0 + e1);
                    cwv[lane]      = e0 * inv;
                    cwv[lane + 32] = e1 * inv;
                }
                MBAR256();
                if (mtid < 64)
                    wwn[mtid] = scal[2] * (scal[1]*asrt[rnk[mtid]] + (1.f-scal[1])*cwv[mtid]);
                MBAR256();
                if (mwarp == 0) {
                    float s = wred_sum(wwn[lane] + wwn[lane+32]);
                    if (lane == 0) scal[4] = s;
                }
#pragma unroll
                for (int i = 0; i < 8; i++) {
                    int e = i*256 + mtid, n = e>>5, w = e&31;
                    Ms[n*33+w] = Ms[n*33+w]*(1.f - wwn[n]*er[w]) + wwn[n]*wv[w];
                }
#pragma unroll
                for (int i = 0; i < 16; i++) {
                    int e = i*256 + mtid, ii = e>>6, jj = e&63;
                    Ls[ii*65+jj] = (ii == jj) ? 0.f
                               : (1.f - wwn[ii] - wwn[jj])*Ls[ii*65+jj] + wwn[ii]*p_s[jj];
                }
                MBAR256();
                if (mtid < 64) {
                    p_s[mtid] = (1.f - scal[4])*p_s[mtid] + wwn[mtid];
                    float ss = EPSf;
                    for (int w = 0; w < 32; w++) ss += Ms[mtid*33+w]*Ms[mtid*33+w];
                    mno[mtid] = rsqrtf(ss);
                }
                MBAR256();
                {
                    int r = mtid >> 6, n = mtid & 63;
                    float d = 0.f;
                    for (int w = 0; w < 32; w++) d += rk[r*32+w]*Ms[n*33+w];
                    crs[r*64+n] = d * mno[n] * scal[5+r] * rs[r];
                    float f = 0.f, bb2 = 0.f;
                    for (int m = 0; m < 64; m++) {
                        float wrm = wro[r*64+m];
                        f   += Ls[n*65+m]*wrm;
                        bb2 += Ls[m*65+n]*wrm;
                    }
                    fws[r*64+n] = f; bws[r*64+n] = bb2;
                }
                MBAR256();
                if (mtid < 128) {
                    int r = mwarp;
                    float v0 = crs[r*64 + lane], v1 = crs[r*64 + 32 + lane];
                    float mx = wred_max(fmaxf(v0, v1));
                    float e0 = expf(v0 - mx), e1 = expf(v1 - mx);
                    float inv = 1.f / wred_sum(e0 + e1);
                    crs[r*64 + lane]      = e0 * inv;
                    crs[r*64 + 32 + lane] = e1 * inv;
                }
                MBAR256();
                {
                    int r = mtid >> 6, n = mtid & 63;
                    wrn[r*64+n] = rmm[r*3+0]*bws[r*64+n] + rmm[r*3+1]*crs[r*64+n] + rmm[r*3+2]*fws[r*64+n];
                }
                MBAR256();
                if (mtid < 128) {
                    int r = mtid >> 5, w = mtid & 31;
                    float s = 0.f;
                    for (int n = 0; n < 64; n++) s += wrn[r*64+n]*Ms[n*33+w];
                    fws[mtid] = s;
                }
                if (mtid < 64) wwo[mtid] = wwn[mtid];
                wro[mtid] = wrn[mtid];
                MBAR256();
                if (mtid < 64) {
                    // rv_t -> current-parity packed buffer, kpairs 384..447
                    ((unsigned*)g_cbH[par])[bid*DKP + 384 + mtid] = pack_h2(fws[2*mtid], fws[2*mtid+1]);
                }
            }
        } else {
            // type B: stage by all 768, k-split matvec
#pragma unroll
            for (int i = 0; i < 8; i++) {
                int q = i*768 + tid;
                int row = q / 96, c4 = q - row*96;
                *(uint4*)(Apk + row*DSTR + c4*4) = *(const uint4*)(srcH + row*DKP + c4*4);
            }
            __syncthreads();
#pragma unroll
            for (int q = 0; q < 12; q++) {
                unsigned off = (unsigned)(ks*12 + q)*64u;
                unsigned ah0[4], ah1[4], bhf[4];
                ldsm4(ah0, aB + off);
                ldsm4(ah1, aB + off + 32u);
                ldsm4(bhf, bB + off);
                mma_f16(D, ah0, bhf);
                mma_f16(D, ah1, bhf+2);
            }
        }
        grid_sync_n(256u + 2u*t);

        // ================= PHASE 2: rv matvec + epilogue =================
        if (typeA) {
            if (warp < 16) {
#pragma unroll
                for (int i = 0; i < 2; i++) {
                    int q = i*512 + tid;
                    if (q < 1024) {
                        int row = q >> 4, c4 = q & 15;
                        *(uint4*)(Apk + row*DSTR + (96 + c4)*4) = *(const uint4*)(srcH + row*DKP + 384 + c4*4);
                    }
                }
                MBAR512();
                if (warp < 12) {
#pragma unroll
                    for (int q = 0; q < 4; q++) {
                        unsigned off = (unsigned)(24 + q)*64u;
                        unsigned ah0[4], ah1[4], bhf[4];
                        ldsm4(ah0, aB + off);
                        ldsm4(ah1, aB + off + 32u);
                        ldsm4(bhf, bB + off);
                        mma_f16(D, ah0, bhf);
                        mma_f16(D, ah1, bhf+2);
                    }
                }
            }
        } else {
#pragma unroll
            for (int i = 0; i < 2; i++) {
                int q = i*768 + tid;
                if (q < 1024) {
                    int row = q >> 4, c4 = q & 15;
                    *(uint4*)(Apk + row*DSTR + (96 + c4)*4) = *(const uint4*)(srcH + row*DKP + 384 + c4*4);
                }
            }
            __syncthreads();
#pragma unroll
            for (int q = 0; q < 2; q++) {
                unsigned off = (unsigned)(24 + ks*2 + q)*64u;
                unsigned ah0[4], ah1[4], bhf[4];
                ldsm4(ah0, aB + off);
                ldsm4(ah1, aB + off + 32u);
                ldsm4(bhf, bB + off);
                mma_f16(D, ah0, bhf);
                mma_f16(D, ah1, bhf+2);
            }
            // ks reduce
            int rslot = ((mt*3 + nt)*32 + lane)*4;
            if (ks == 1) *(float4*)&red[rslot] = make_float4(D[0], D[1], D[2], D[3]);
            __syncthreads();
            if (ks == 0) {
                float4 rr = *(const float4*)&red[rslot];
                D[0] += rr.x; D[1] += rr.y; D[2] += rr.z; D[3] += rr.w;
            }
        }
        // epilogue on warps 0..11 (both types)
        if (epi_own) {
            float p0 = __shfl_xor_sync(0xffffffffu, D[0], 1);
            float p1 = __shfl_xor_sync(0xffffffffu, D[1], 1);
            float p2 = __shfl_xor_sync(0xffffffffu, D[2], 1);
            float p3 = __shfl_xor_sync(0xffffffffu, D[3], 1);
            float hn = 0.f;
            if (jv) {
                float ai, af, ag, ao;
                if (S == 0) { ai = D[0]; af = D[1]; ag = p0; ao = p1; }
                else        { ai = p2;  af = p3;  ag = D[2]; ao = D[3]; }
                float gi = pj0 + ai, gf = pj1 + af, gg = pj2 + ag, go = pj3 + ao;
                cst = sigm(gf)*cst + sigm(gi)*tanhf(gg);
                hn = sigm(go)*tanhf(cst);
                if (j < Hh) out[((size_t)b*Tt + t)*Hh + j] = hn;
                else        combW[j*Bb + b] = hn;
            }
            float hn2 = __shfl_xor_sync(0xffffffffu, hn, 2);
            if (jh == 0 && jv) {
                int kp = (jb + nt*2) >> 1;
                dstH[b*DKP + kp] = pack_h2(hn, hn2);
            }
        }
        grid_sync_n(257u + 2u*t);
    }
}

extern "C" void kernel_launch(void* const* d_in, const int* in_sizes, int n_in,
                              void* d_out, int out_size) {
    const float* x     = (const float*)d_in[0];
    const float* Wih_e = (const float*)d_in[1];
    const float* Whh_e = (const float*)d_in[2];
    const float* b_e   = (const float*)d_in[3];
    const float* Wih_c = (const float*)d_in[4];
    const float* Whh_c = (const float*)d_in[5];
    const float* b_c   = (const float*)d_in[6];
    float* out = (float*)d_out;

    static int attrs_set = 0;
    if (!attrs_set) {
        cudaFuncSetAttribute(enc_persist, cudaFuncAttributeMaxDynamicSharedMemorySize, E_SM_U32*4);
        cudaFuncSetAttribute(dnc_persist, cudaFuncAttributeMaxDynamicSharedMemorySize, D_SM_U32*4);
        cudaFuncSetAttribute(gemm_tf32, cudaFuncAttributeMaxDynamicSharedMemorySize, GEMM_SMEM);
        attrs_set = 1;
    }

    float* xprojT; cudaGetSymbolAddress((void**)&xprojT, g_xprojT);
    float* eprojT; cudaGetSymbolAddress((void**)&eprojT, g_eprojT);

    zero_bufs<<<64, 256>>>();

    gemm_tf32<<<dim3(32, 128), 256, GEMM_SMEM>>>(x, Wih_e, b_e, xprojT, G4E, 512, 1);

    enc_persist<<<NBLK, 512, E_SM_U32*4>>>(Whh_e);

    gemm_tf32<<<dim3(48, 128), 256, GEMM_SMEM>>>(nullptr, Wih_c, b_c, eprojT, G4C, 640, 0);

    dnc_persist<<<NBLK, 768, D_SM_U32*4>>>(Whh_c, Wih_c, out);
}

// round 17
// speedup vs baseline: 1.4233x; 1.4233x over previous
#include <cuda_runtime.h>
#include <cuda_fp16.h>
#include <math.h>

#define Hh   512
#define Rr   4
#define Ww   32
#define Nn   64
#define Bb   64
#define Tt   256
#define HIDC 759
#define G4C  3036
#define G4E  2048
#define EPSf 1e-6f

#define NBLK 128

// packed-k geometry: h occupies k 0..758, k=759 zero pad, rv at k 760..887, zero to 895
#define DKP  448            // dnc k-pairs (896/2)
#define EKP  256            // enc k-pairs (512/2)
#define DSTR 452            // dnc SMEM row stride (u32), 452 % 32 == 4 -> conflict-free ldmatrix
#define ESTR 260            // enc SMEM row stride (u32), 260 % 32 == 4

typedef unsigned long long ull;

// ---- global buffers ----
__device__ float    g_comb[2][HIDC*Bb];               // fp32 h (machinery interface region used)
__device__ unsigned g_cbH[2][Bb*DKP];                 // dnc packed comb (fp16 pairs) [b][kpair]
__device__ unsigned g_ehH[2][Bb*EKP];                 // enc packed h
__device__ float    g_xprojT[(size_t)Tt*G4E*Bb];      // [t][col][b]
__device__ float    g_eprojT[(size_t)Tt*G4C*Bb];      // [t][col][b]
__device__ float    g_encT  [(size_t)Tt*Hh*Bb];       // [t][j][b]

__device__ unsigned g_cnt1[8*32];
__device__ unsigned g_cnt2;
__device__ volatile unsigned g_gen;

__device__ __forceinline__ float sigm(float x)  { return 1.f/(1.f+expf(-x)); }
__device__ __forceinline__ float splus(float x) { return x > 0.f ? x + log1pf(expf(-x)) : log1pf(expf(x)); }

__device__ __forceinline__ float wred_max(float v) {
#pragma unroll
    for (int s = 16; s > 0; s >>= 1) v = fmaxf(v, __shfl_xor_sync(0xffffffffu, v, s));
    return v;
}
__device__ __forceinline__ float wred_sum(float v) {
#pragma unroll
    for (int s = 16; s > 0; s >>= 1) v += __shfl_xor_sync(0xffffffffu, v, s);
    return v;
}

__device__ __forceinline__ unsigned pack_h2(float v0, float v1) {
    __half2 h = __floats2half2_rn(v0, v1);
    return *(unsigned*)&h;
}

__device__ __forceinline__ void mma_f16(float c[4], const unsigned a[4], const unsigned* b) {
    asm volatile("mma.sync.aligned.m16n8k16.row.col.f32.f16.f16.f32 "
        "{%0,%1,%2,%3}, {%4,%5,%6,%7}, {%8,%9}, {%0,%1,%2,%3};"
        : "+f"(c[0]), "+f"(c[1]), "+f"(c[2]), "+f"(c[3])
        : "r"(a[0]), "r"(a[1]), "r"(a[2]), "r"(a[3]), "r"(b[0]), "r"(b[1]));
}

__device__ __forceinline__ void ldsm4(unsigned r[4], unsigned addr) {
    asm volatile("ldmatrix.sync.aligned.m8n8.x4.shared.b16 {%0,%1,%2,%3}, [%4];"
        : "=r"(r[0]), "=r"(r[1]), "=r"(r[2]), "=r"(r[3]) : "r"(addr));
}

__device__ __forceinline__ unsigned smem_u32(const void* p) {
    return (unsigned)__cvta_generic_to_shared(p);
}

__device__ __forceinline__ void grid_sync_n(unsigned n) {
    __syncthreads();
    if (threadIdx.x == 0) {
        __threadfence();
        unsigned old = atomicAdd(&g_cnt1[(blockIdx.x & 7) * 32], 1u);
        if (old == n * 16u + 15u) {
            unsigned o2 = atomicAdd(&g_cnt2, 1u);
            if (o2 == n * 8u + 7u) {
                __threadfence();
                g_gen = n + 1u;
            }
        }
        while (g_gen < n + 1u) __nanosleep(32);
        __threadfence();
    }
    __syncthreads();
}

__global__ void zero_bufs() {
    int ncb = 2*Bb*DKP, neh = 2*Bb*EKP;
    int stride = gridDim.x*blockDim.x, tid0 = blockIdx.x*blockDim.x + threadIdx.x;
    for (int i = tid0; i < ncb; i += stride) ((unsigned*)g_cbH)[i] = 0u;
    for (int i = tid0; i < neh; i += stride) ((unsigned*)g_ehH)[i] = 0u;
    if (blockIdx.x == 0) {
        if (threadIdx.x < 8)       g_cnt1[threadIdx.x*32] = 0u;
        else if (threadIdx.x == 8) g_cnt2 = 0u;
        else if (threadIdx.x == 9) g_gen = 0u;
    }
}

// ================= split-tf32 tensor-core prep GEMM (unchanged) =================
__device__ __forceinline__ void split_tf32(float v, float& hi, float& lo) {
    hi = __uint_as_float(__float_as_uint(v) & 0xFFFFE000u);
    lo = v - hi;
}
__device__ __forceinline__ void mma_tf32(float c[4], const unsigned a[4], const unsigned b[2]) {
    asm volatile("mma.sync.aligned.m16n8k8.row.col.f32.tf32.tf32.f32 "
        "{%0,%1,%2,%3}, {%4,%5,%6,%7}, {%8,%9}, {%0,%1,%2,%3};"
        : "+f"(c[0]), "+f"(c[1]), "+f"(c[2]), "+f"(c[3])
        : "r"(a[0]), "r"(a[1]), "r"(a[2]), "r"(a[3]), "r"(b[0]), "r"(b[1]));
}

#define GA (128*33)
#define GB (64*33)
#define GEMM_SMEM ((2*GA + 2*GB)*4)

__global__ void __launch_bounds__(256, 1) gemm_tf32(
    const float* __restrict__ x, const float* __restrict__ Wm,
    const float* __restrict__ bias, float* __restrict__ proj,
    int Ncols, int ldw, int xmode)
{
    extern __shared__ __align__(16) float gsm[];
    float* Ah = gsm;
    float* Al = gsm + GA;
    float* Bh = gsm + 2*GA;
    float* Bl = gsm + 2*GA + GB;

    int tid = threadIdx.x, warp = tid >> 5, lane = tid & 31;
    int wm = warp & 3, wn = warp >> 2;
    int g = lane >> 2, tg = lane & 3;
    int row0 = blockIdx.y * 128, col0 = blockIdx.x * 64;

    float acc[2][4][4];
#pragma unroll
    for (int i = 0; i < 2; i++)
#pragma unroll
        for (int j = 0; j < 4; j++)
#pragma unroll
            for (int e = 0; e < 4; e++) acc[i][j][e] = 0.f;

    for (int k0 = 0; k0 < 512; k0 += 32) {
        __syncthreads();
        if (xmode) {
#pragma unroll
            for (int i = 0; i < 4; i++) {
                int q = i*256 + tid;
                int m = q >> 3, kk = (q & 7) * 4;
                int r = row0 + m;
                float4 v = *(const float4*)(x + ((size_t)(r & 63) * Tt + (r >> 6)) * Hh + k0 + kk);
                float h, l;
                split_tf32(v.x, h, l); Ah[m*33+kk  ] = h; Al[m*33+kk  ] = l;
                split_tf32(v.y, h, l); Ah[m*33+kk+1] = h; Al[m*33+kk+1] = l;
                split_tf32(v.z, h, l); Ah[m*33+kk+2] = h; Al[m*33+kk+2] = l;
                split_tf32(v.w, h, l); Ah[m*33+kk+3] = h; Al[m*33+kk+3] = l;
            }
        } else {
#pragma unroll
            for (int i = 0; i < 4; i++) {
                int q = i*256 + tid;
                int tt = q >> 9, kk = (q >> 4) & 31, b4 = (q & 15) * 4;
                float4 v = *(const float4*)(g_encT + ((size_t)((row0 >> 6) + tt) * Hh + k0 + kk) * Bb + b4);
                int m = tt*64 + b4;
                float h, l;
                split_tf32(v.x, h, l); Ah[(m  )*33+kk] = h; Al[(m  )*33+kk] = l;
                split_tf32(v.y, h, l); Ah[(m+1)*33+kk] = h; Al[(m+1)*33+kk] = l;
                split_tf32(v.z, h, l); Ah[(m+2)*33+kk] = h; Al[(m+2)*33+kk] = l;
                split_tf32(v.w, h, l); Ah[(m+3)*33+kk] = h; Al[(m+3)*33+kk] = l;
            }
        }
#pragma unroll
        for (int i = 0; i < 2; i++) {
            int q = i*256 + tid;
            int cc = q >> 3, kk = (q & 7) * 4;
            int cg = col0 + cc;
            float4 v = make_float4(0.f, 0.f, 0.f, 0.f);
            if (cg < Ncols) v = *(const float4*)(Wm + (size_t)cg * ldw + k0 + kk);
            float h, l;
            split_tf32(v.x, h, l); Bh[cc*33+kk  ] = h; Bl[cc*33+kk  ] = l;
            split_tf32(v.y, h, l); Bh[cc*33+kk+1] = h; Bl[cc*33+kk+1] = l;
            split_tf32(v.z, h, l); Bh[cc*33+kk+2] = h; Bl[cc*33+kk+2] = l;
            split_tf32(v.w, h, l); Bh[cc*33+kk+3] = h; Bl[cc*33+kk+3] = l;
        }
        __syncthreads();

#pragma unroll
        for (int kg = 0; kg < 4; kg++) {
            int kb = kg*8;
            unsigned ah[2][4], al[2][4], bh[4][2], bl[4][2];
#pragma unroll
            for (int mt = 0; mt < 2; mt++) {
                int r0 = (wm*32 + mt*16 + g) * 33 + kb + tg;
                int r1 = r0 + 8*33;
                ah[mt][0] = __float_as_uint(Ah[r0]);
                ah[mt][1] = __float_as_uint(Ah[r1]);
                ah[mt][2] = __float_as_uint(Ah[r0 + 4]);
                ah[mt][3] = __float_as_uint(Ah[r1 + 4]);
                al[mt][0] = __float_as_uint(Al[r0]);
                al[mt][1] = __float_as_uint(Al[r1]);
                al[mt][2] = __float_as_uint(Al[r0 + 4]);
                al[mt][3] = __float_as_uint(Al[r1 + 4]);
            }
#pragma unroll
            for (int nt = 0; nt < 4; nt++) {
                int ci = (wn*32 + nt*8 + g) * 33 + kb + tg;
                bh[nt][0] = __float_as_uint(Bh[ci]);
                bh[nt][1] = __float_as_uint(Bh[ci + 4]);
                bl[nt][0] = __float_as_uint(Bl[ci]);
                bl[nt][1] = __float_as_uint(Bl[ci + 4]);
            }
#pragma unroll
            for (int mt = 0; mt < 2; mt++)
#pragma unroll
                for (int nt = 0; nt < 4; nt++) {
                    mma_tf32(acc[mt][nt], ah[mt], bh[nt]);
                    mma_tf32(acc[mt][nt], ah[mt], bl[nt]);
                    mma_tf32(acc[mt][nt], al[mt], bh[nt]);
                }
        }
    }
#pragma unroll
    for (int mt = 0; mt < 2; mt++) {
        int rbase = row0 + wm*32 + mt*16 + g;
#pragma unroll
        for (int nt = 0; nt < 4; nt++) {
            int cb = col0 + wn*32 + nt*8 + 2*tg;
#pragma unroll
            for (int e = 0; e < 4; e++) {
                int r = rbase + ((e >= 2) ? 8 : 0);
                int cix = cb + (e & 1);
                if (cix < Ncols)
                    proj[((size_t)(r >> 6) * Ncols + cix) * Bb + (r & 63)] = acc[mt][nt][e] + bias[cix];
            }
        }
    }
}

// ============ persistent encoder: 128 blocks x 512 threads (mt4 x nt2 x ks2), full-A resident ============
#define E_SM_U32 (16*ESTR + 64*ESTR + 1024)

__global__ void __launch_bounds__(512, 1) enc_persist(const float* __restrict__ Whh) {
    extern __shared__ __align__(16) unsigned smu[];
    unsigned* BpkH = smu;                  // 16 x ESTR
    unsigned* Apk  = BpkH + 16*ESTR;       // 64 x ESTR
    float*    red  = (float*)(Apk + 64*ESTR);  // 1024

    int tid = threadIdx.x, bid = blockIdx.x;
    int jb = bid * 4;
    int warp = tid >> 5, lane = tid & 31;
    int mt = warp & 3, nt = (warp >> 2) & 1, ks = warp >> 3;
    int g = lane >> 2, tg = lane & 3;
    int S = tg & 1, jh = tg >> 1;
    int b = mt*16 + g + 8*S;
    int j = jb + nt*2 + jh;

    for (int idx = tid; idx < 16*EKP; idx += 512) {
        int c = idx >> 8, kp = idx & 255;
        int jl = c >> 2, gg = c & 3;
        int jw = jb + jl;
        float v0 = Whh[((size_t)(gg*Hh + jw))*Hh + 2*kp];
        float v1 = Whh[((size_t)(gg*Hh + jw))*Hh + 2*kp + 1];
        BpkH[c*ESTR + kp] = pack_h2(v0, v1);
    }
    float cst = 0.f;

    int rowA = mt*16 + (lane & 15);
    unsigned aB = smem_u32(Apk) + (unsigned)(rowA*ESTR + (lane >> 4)*4)*4u;
    int rowB = nt*8 + (lane & 7);
    unsigned bB = smem_u32(BpkH) + (unsigned)(rowB*ESTR + ((lane >> 3)&3)*4)*4u;

    for (int t = 0; t < Tt; t++) {
        int par = t & 1;
        const unsigned* srcH = g_ehH[par];

        const float* xp = g_xprojT + (size_t)t*G4E*Bb;
        float pj0 = __ldg(&xp[((size_t)(0*Hh + j))*Bb + b]);
        float pj1 = __ldg(&xp[((size_t)(1*Hh + j))*Bb + b]);
        float pj2 = __ldg(&xp[((size_t)(2*Hh + j))*Bb + b]);
        float pj3 = __ldg(&xp[((size_t)(3*Hh + j))*Bb + b]);

#pragma unroll
        for (int i = 0; i < 8; i++) {
            int q = i*512 + tid;
            int row = q >> 6, c4 = q & 63;
            *(uint4*)(Apk + row*ESTR + c4*4) = *(const uint4*)(srcH + row*EKP + c4*4);
        }
        __syncthreads();

        float D[4] = {0.f, 0.f, 0.f, 0.f};
#pragma unroll
        for (int q = 0; q < 8; q++) {
            unsigned off = (unsigned)(ks*8 + q)*64u;
            unsigned ah0[4], ah1[4], bhf[4];
            ldsm4(ah0, aB + off);
            ldsm4(ah1, aB + off + 32u);
            ldsm4(bhf, bB + off);
            mma_f16(D, ah0, bhf);
            mma_f16(D, ah1, bhf+2);
        }
        int rslot = ((mt + 4*nt)*32 + lane)*4;
        if (ks == 1) *(float4*)&red[rslot] = make_float4(D[0], D[1], D[2], D[3]);
        __syncthreads();
        if (ks == 0) {
            float4 rr = *(const float4*)&red[rslot];
            D[0] += rr.x; D[1] += rr.y; D[2] += rr.z; D[3] += rr.w;
            float p0 = __shfl_xor_sync(0xffffffffu, D[0], 1);
            float p1 = __shfl_xor_sync(0xffffffffu, D[1], 1);
            float p2 = __shfl_xor_sync(0xffffffffu, D[2], 1);
            float p3 = __shfl_xor_sync(0xffffffffu, D[3], 1);
            float ai, af, ag, ao;
            if (S == 0) { ai = D[0]; af = D[1]; ag = p0; ao = p1; }
            else        { ai = p2;  af = p3;  ag = D[2]; ao = D[3]; }
            float gi = pj0 + ai, gf = pj1 + af, gg = pj2 + ag, go = pj3 + ao;
            cst = sigm(gf)*cst + sigm(gi)*tanhf(gg);
            float hn = sigm(go)*tanhf(cst);
            g_encT[((size_t)t*Hh + j)*Bb + b] = hn;
            float hn2 = __shfl_xor_sync(0xffffffffu, hn, 2);
            if (jh == 0) {
                int kp = (jb + nt*2) >> 1;
                g_ehH[par^1][b*EKP + kp] = pack_h2(hn, hn2);
            }
        }
        grid_sync_n(t);
    }
}

// ============ persistent DNC: 128 blocks x 768 threads (mt4 x nt3 x ks2), full-A + wide machinery ============
#define MEM_F  8512
#define D_SM_U32 (24*DSTR + 64*DSTR + 1536 + MEM_F)

__global__ void __launch_bounds__(768, 1) dnc_persist(const float* __restrict__ Whh_c,
                                                      const float* __restrict__ Wih_c,
                                                      float* __restrict__ out) {
    extern __shared__ __align__(16) unsigned smu[];
    unsigned* BpkH = smu;                  // 24 x DSTR
    unsigned* Apk  = BpkH + 24*DSTR;       // 64 x DSTR
    float*    red  = (float*)(Apk + 64*DSTR);  // 1536
    float*    MEM  = red + 1536;

    float* Ms   = MEM;
    float* Ls   = MEM + 2112;
    float* u_s  = MEM + 6272;
    float* p_s  = u_s + 64;
    float* wwo  = p_s + 64;
    float* wwn  = wwo + 64;
    float* su   = wwn + 64;
    float* asrt = su + 64;
    float* cwv  = asrt + 64;
    float* simv = cwv + 64;
    float* mno  = simv + 64;
    int*   rnk  = (int*)(mno + 64);
    float* wro  = mno + 128;
    float* wrn  = wro + 256;
    float* crs  = wrn + 256;
    float* fws  = crs + 256;
    float* bws  = fws + 256;
    float* rk   = bws + 256;
    float* wk   = rk + 128;
    float* er   = wk + 32;
    float* wv   = er + 32;
    float* rs   = wv + 32;
    float* fg   = rs + 4;
    float* rmm  = fg + 4;
    float* rmraw= rmm + 12;
    float* scal = rmraw + 12;

    int tid = threadIdx.x, bid = blockIdx.x;
    int jb = bid * 6;
    int warp = tid >> 5, lane = tid & 31;
    int mt = warp & 3;
    int ntks = warp >> 2;                 // 0..5
    int nt = ntks % 3, ks = ntks / 3;
    int g = lane >> 2, tg = lane & 3;
    int S = tg & 1, jh = tg >> 1;
    int b = mt*16 + g + 8*S;
    int j = jb + nt*2 + jh;
    bool jv = j < HIDC;
    int jsafe = jv ? j : 0;

    // weights -> fp16 packed [col][kpair]
    for (int idx = tid; idx < 24*DKP; idx += 768) {
        int c = idx / DKP, kp = idx - c*DKP;
        int jl = c >> 2, gg = c & 3;
        int jw = jb + jl;
        float v0 = 0.f, v1 = 0.f;
        if (jw < HIDC) {
            int k0 = 2*kp, k1 = 2*kp + 1;
            if (k0 < HIDC) v0 = Whh_c[((size_t)(gg*HIDC + jw))*HIDC + k0];
            else if (k0 >= 760 && k0 < 888) v0 = Wih_c[((size_t)(gg*HIDC + jw))*640 + 512 + (k0 - 760)];
            if (k1 < HIDC) v1 = Whh_c[((size_t)(gg*HIDC + jw))*HIDC + k1];
            else if (k1 >= 760 && k1 < 888) v1 = Wih_c[((size_t)(gg*HIDC + jw))*640 + 512 + (k1 - 760)];
        }
        BpkH[c*DSTR + kp] = pack_h2(v0, v1);
    }
    if (bid < 64) {
        for (int idx = tid; idx < MEM_F; idx += 768) MEM[idx] = 0.f;
    }
    float cst = 0.f;

    int rowA = mt*16 + (lane & 15);
    unsigned aB = smem_u32(Apk) + (unsigned)(rowA*DSTR + (lane >> 4)*4)*4u;
    int rowB = nt*8 + (lane & 7);
    unsigned bB = smem_u32(BpkH) + (unsigned)(rowB*DSTR + ((lane >> 3)&3)*4)*4u;

    for (int t = 0; t < Tt; t++) {
        int par = t & 1;
        int np = par ^ 1;
        const unsigned* srcH = g_cbH[par];
        float* combN = g_comb[np];

        const float* ep = g_eprojT + (size_t)t*G4C*Bb;
        float pj0 = __ldg(&ep[((size_t)(0*HIDC + jsafe))*Bb + b]);
        float pj1 = __ldg(&ep[((size_t)(1*HIDC + jsafe))*Bb + b]);
        float pj2 = __ldg(&ep[((size_t)(2*HIDC + jsafe))*Bb + b]);
        float pj3 = __ldg(&ep[((size_t)(3*HIDC + jsafe))*Bb + b]);

        // stage full A: 64 rows x 112 uint4 = 7168
#pragma unroll
        for (int i = 0; i < 10; i++) {
            int q = i*768 + tid;
            if (q < 7168) {
                int row = q / 112, c4 = q - row*112;
                *(uint4*)(Apk + row*DSTR + c4*4) = *(const uint4*)(srcH + row*DKP + c4*4);
            }
        }
        __syncthreads();

        float D[4] = {0.f, 0.f, 0.f, 0.f};
#pragma unroll
        for (int q = 0; q < 14; q++) {
            unsigned off = (unsigned)(ks*14 + q)*64u;
            unsigned ah0[4], ah1[4], bhf[4];
            ldsm4(ah0, aB + off);
            ldsm4(ah1, aB + off + 32u);
            ldsm4(bhf, bB + off);
            mma_f16(D, ah0, bhf);
            mma_f16(D, ah1, bhf+2);
        }
        int rslot = ((mt*3 + nt)*32 + lane)*4;
        if (ks == 1) *(float4*)&red[rslot] = make_float4(D[0], D[1], D[2], D[3]);
        __syncthreads();
        if (ks == 0) {
            float4 rr = *(const float4*)&red[rslot];
            D[0] += rr.x; D[1] += rr.y; D[2] += rr.z; D[3] += rr.w;
            float p0 = __shfl_xor_sync(0xffffffffu, D[0], 1);
            float p1 = __shfl_xor_sync(0xffffffffu, D[1], 1);
            float p2 = __shfl_xor_sync(0xffffffffu, D[2], 1);
            float p3 = __shfl_xor_sync(0xffffffffu, D[3], 1);
            float hn = 0.f;
            if (jv) {
                float ai, af, ag, ao;
                if (S == 0) { ai = D[0]; af = D[1]; ag = p0; ao = p1; }
                else        { ai = p2;  af = p3;  ag = D[2]; ao = D[3]; }
                float gi = pj0 + ai, gf = pj1 + af, gg = pj2 + ag, go = pj3 + ao;
                cst = sigm(gf)*cst + sigm(gi)*tanhf(gg);
                hn = sigm(go)*tanhf(cst);
                if (j < Hh) out[((size_t)b*Tt + t)*Hh + j] = hn;
                else        combN[j*Bb + b] = hn;
            }
            float hn2 = __shfl_xor_sync(0xffffffffu, hn, 2);
            if (jh == 0 && jv) {
                int kp = (jb + nt*2) >> 1;
                g_cbH[np][b*DKP + kp] = pack_h2(hn, hn2);
            }
        }
        grid_sync_n(256u + 2u*t);

        // ---------------- memory machinery: blocks 0..63, ALL 768 threads ----------------
        if (bid < 64) {
            int mb = bid;
            if (tid < 247) {
                float v = __ldcg(&combN[(Hh + tid)*Bb + mb]);
                if      (tid < 128) rk[tid] = tanhf(v);
                else if (tid < 132) rs[tid-128] = splus(v);
                else if (tid < 164) wk[tid-132] = tanhf(v);
                else if (tid ==164) scal[0] = splus(v);
                else if (tid < 197) er[tid-165] = sigm(v);
                else if (tid < 229) wv[tid-197] = tanhf(v);
                else if (tid < 233) fg[tid-229] = sigm(v);
                else if (tid ==233) scal[1] = sigm(v);
                else if (tid ==234) scal[2] = sigm(v);
                else                rmraw[tid-235] = v;
            }
            __syncthreads();
            if (tid < 4) {
                float x0=rmraw[tid*3], x1=rmraw[tid*3+1], x2=rmraw[tid*3+2];
                float m = fmaxf(x0, fmaxf(x1, x2));
                float e0=expf(x0-m), e1=expf(x1-m), e2=expf(x2-m), s=e0+e1+e2;
                rmm[tid*3]=e0/s; rmm[tid*3+1]=e1/s; rmm[tid*3+2]=e2/s;
            } else if (tid == 4) {
                float s = EPSf;
                for (int w = 0; w < 32; w++) s += wk[w]*wk[w];
                scal[3] = rsqrtf(s);
            } else if (tid >= 8 && tid < 12) {
                int r = tid - 8; float s = EPSf;
                for (int w = 0; w < 32; w++) s += rk[r*32+w]*rk[r*32+w];
                scal[5+r] = rsqrtf(s);
            } else if (tid >= 64 && tid < 128) {
                int n = tid - 64;
                float psi = 1.f;
#pragma unroll
                for (int r = 0; r < 4; r++) psi *= 1.f - fg[r]*wro[r*64+n];
                float uo = u_s[n], w = wwo[n];
                u_s[n] = (uo + w - uo*w) * psi;
            }
            __syncthreads();
            if (tid < 64) {
                float un = u_s[tid]; int r = 0;
                for (int m = 0; m < 64; m++) {
                    float um = u_s[m];
                    r += (um < un) || (um == un && m < tid);
                }
                rnk[tid] = r;
                su[r] = un;
            } else if (tid < 128) {
                int n = tid - 64; float ss = EPSf, d = 0.f;
                for (int w = 0; w < 32; w++) { float m = Ms[n*33+w]; ss += m*m; d += wk[w]*m; }
                simv[n] = d * rsqrtf(ss) * scal[3];
            }
            __syncthreads();
            if (warp == 1) {
                float a0 = su[lane], a1 = su[lane+32];
                float s0 = a0, s1 = a1;
#pragma unroll
                for (int d = 1; d < 32; d <<= 1) {
                    float t0 = __shfl_up_sync(0xffffffffu, s0, d);
                    float t1 = __shfl_up_sync(0xffffffffu, s1, d);
                    if (lane >= d) { s0 *= t0; s1 *= t1; }
                }
                float tot0 = __shfl_sync(0xffffffffu, s0, 31);
                float u0 = __shfl_up_sync(0xffffffffu, s0, 1);
                float u1 = __shfl_up_sync(0xffffffffu, s1, 1);
                float e0 = lane ? u0 : 1.f;
                float e1 = (lane ? u1 : 1.f) * tot0;
                asrt[lane]      = (1.f - a0) * e0;
                asrt[lane + 32] = (1.f - a1) * e1;
            }
            if (warp == 0) {
                float v0 = simv[lane]*scal[0], v1 = simv[lane+32]*scal[0];
                float mx = wred_max(fmaxf(v0, v1));
                float e0 = expf(v0 - mx), e1 = expf(v1 - mx);
                float inv = 1.f / wred_sum(e0 + e1);
                cwv[lane]      = e0 * inv;
                cwv[lane + 32] = e1 * inv;
            }
            __syncthreads();
            if (tid < 64)
                wwn[tid] = scal[2] * (scal[1]*asrt[rnk[tid]] + (1.f-scal[1])*cwv[tid]);
            __syncthreads();
            if (warp == 0) {
                float s = wred_sum(wwn[lane] + wwn[lane+32]);
                if (lane == 0) scal[4] = s;
            }
            // M update (2048) + L update (4096) over 768 threads
#pragma unroll
            for (int i = 0; i < 3; i++) {
                int e = i*768 + tid;
                if (e < 2048) {
                    int n = e>>5, w = e&31;
                    Ms[n*33+w] = Ms[n*33+w]*(1.f - wwn[n]*er[w]) + wwn[n]*wv[w];
                }
            }
#pragma unroll
            for (int i = 0; i < 6; i++) {
                int e = i*768 + tid;
                if (e < 4096) {
                    int ii = e>>6, jj2 = e&63;
                    Ls[ii*65+jj2] = (ii == jj2) ? 0.f
                               : (1.f - wwn[ii] - wwn[jj2])*Ls[ii*65+jj2] + wwn[ii]*p_s[jj2];
                }
            }
            __syncthreads();
            if (tid < 64) {
                p_s[tid] = (1.f - scal[4])*p_s[tid] + wwn[tid];
                float ss = EPSf;
                for (int w = 0; w < 32; w++) ss += Ms[tid*33+w]*Ms[tid*33+w];
                mno[tid] = rsqrtf(ss);
            }
            __syncthreads();
            // P6 split: 256 items x 3 m-segments over 768 threads
            {
                int item = tid & 255, seg = tid >> 8;       // seg 0..2
                int r = item >> 6, n = item & 63;
                const int m0s[3] = {0, 21, 42}, m1s[3] = {21, 42, 64};
                float f = 0.f, bb2 = 0.f;
                for (int m = m0s[seg]; m < m1s[seg]; m++) {
                    float wrm = wro[r*64+m];
                    f   += Ls[n*65+m]*wrm;
                    bb2 += Ls[m*65+n]*wrm;
                }
                red[tid] = f;
                red[768 + tid] = bb2;
                if (seg == 0) {
                    float d = 0.f;
                    for (int w = 0; w < 32; w++) d += rk[r*32+w]*Ms[n*33+w];
                    crs[item] = d * mno[n] * scal[5+r] * rs[r];
                }
            }
            __syncthreads();
            if (tid < 256) {
                fws[tid] = red[tid] + red[256+tid] + red[512+tid];
                bws[tid] = red[768+tid] + red[1024+tid] + red[1280+tid];
            }
            __syncthreads();
            if (tid < 128) {
                int r = warp;
                float v0 = crs[r*64 + lane], v1 = crs[r*64 + 32 + lane];
                float mx = wred_max(fmaxf(v0, v1));
                float e0 = expf(v0 - mx), e1 = expf(v1 - mx);
                float inv = 1.f / wred_sum(e0 + e1);
                crs[r*64 + lane]      = e0 * inv;
                crs[r*64 + 32 + lane] = e1 * inv;
            }
            __syncthreads();
            if (tid < 256) {
                int r = tid >> 6, n = tid & 63;
                wrn[r*64+n] = rmm[r*3+0]*bws[r*64+n] + rmm[r*3+1]*crs[r*64+n] + rmm[r*3+2]*fws[r*64+n];
            }
            __syncthreads();
            // P9 split: 128 items x 6 n-segments
            {
                int item = tid & 127, seg = tid >> 7;       // seg 0..5
                int r = item >> 5, w = item & 31;
                int n0 = (seg*64)/6, n1 = ((seg+1)*64)/6;
                float s = 0.f;
                for (int n = n0; n < n1; n++) s += wrn[r*64+n]*Ms[n*33+w];
                red[tid] = s;
            }
            if (tid < 256) wro[tid] = wrn[tid];
            if (tid >= 256 && tid < 320) wwo[tid-256] = wwn[tid-256];
            __syncthreads();
            if (tid < 128) {
                float s = red[tid] + red[128+tid] + red[256+tid]
                        + red[384+tid] + red[512+tid] + red[640+tid];
                fws[tid] = s;
            }
            __syncthreads();
            if (tid < 64) {
                g_cbH[np][mb*DKP + 380 + tid] = pack_h2(fws[2*tid], fws[2*tid+1]);
            }
        }
        grid_sync_n(257u + 2u*t);
    }
}

extern "C" void kernel_launch(void* const* d_in, const int* in_sizes, int n_in,
                              void* d_out, int out_size) {
    const float* x     = (const float*)d_in[0];
    const float* Wih_e = (const float*)d_in[1];
    const float* Whh_e = (const float*)d_in[2];
    const float* b_e   = (const float*)d_in[3];
    const float* Wih_c = (const float*)d_in[4];
    const float* Whh_c = (const float*)d_in[5];
    const float* b_c   = (const float*)d_in[6];
    float* out = (float*)d_out;

    static int attrs_set = 0;
    if (!attrs_set) {
        cudaFuncSetAttribute(enc_persist, cudaFuncAttributeMaxDynamicSharedMemorySize, E_SM_U32*4);
        cudaFuncSetAttribute(dnc_persist, cudaFuncAttributeMaxDynamicSharedMemorySize, D_SM_U32*4);
        cudaFuncSetAttribute(gemm_tf32, cudaFuncAttributeMaxDynamicSharedMemorySize, GEMM_SMEM);
        attrs_set = 1;
    }

    float* xprojT; cudaGetSymbolAddress((void**)&xprojT, g_xprojT);
    float* eprojT; cudaGetSymbolAddress((void**)&eprojT, g_eprojT);

    zero_bufs<<<64, 256>>>();

    gemm_tf32<<<dim3(32, 128), 256, GEMM_SMEM>>>(x, Wih_e, b_e, xprojT, G4E, 512, 1);

    enc_persist<<<NBLK, 512, E_SM_U32*4>>>(Whh_e);

    gemm_tf32<<<dim3(48, 128), 256, GEMM_SMEM>>>(nullptr, Wih_c, b_c, eprojT, G4C, 640, 0);

    dnc_persist<<<NBLK, 768, D_SM_U32*4>>>(Whh_c, Wih_c, out);
}